// round 13
// baseline (speedup 1.0000x reference)
#include <cuda_runtime.h>
#include <cuda_bf16.h>
#include <cstdint>
#include <math.h>

// Problem constants (B=4, L=2048, H=8, E=64)
#define BB 4
#define LL 2048
#define HH 8
#define EE 64
#define NBH (BB*HH)           // 32
#define NROWS (NBH*LL)        // 65536
#define SCALEF 0.125f
#define STRIDE_L (HH*EE)      // 512
#define TILE_B 16384          // one 128x64 bf16 tile, swizzled, bytes

// Scratch (device globals — allocation-free)
__device__ float g_sigv[NROWS];
__device__ float g_coef[NROWS];
__device__ float g_inv2s2[NROWS];
// Pre-converted bf16 hi/lo tiles in EXACT swizzled smem byte layout.
// Index: ((bh*16 + tile) * TILE_B). 6 x 8MB = 48MB.
__device__ __align__(16) unsigned char g_qhi[NBH * 16 * TILE_B];
__device__ __align__(16) unsigned char g_qlo[NBH * 16 * TILE_B];
__device__ __align__(16) unsigned char g_khi[NBH * 16 * TILE_B];
__device__ __align__(16) unsigned char g_klo[NBH * 16 * TILE_B];
__device__ __align__(16) unsigned char g_vhi[NBH * 16 * TILE_B];
__device__ __align__(16) unsigned char g_vlo[NBH * 16 * TILE_B];

// ---- smem layout (bytes). Q tiles + double-buffered K/V tile groups ----
#define OFF_INV   0            // 128 f32 rowsum reciprocals
#define OFF_QHI   1024
#define OFF_QLO   17408
#define OFF_BUF0  33792        // [KHI,KLO,VHI,VLO] x 16KB = 64KB
#define OFF_BUF1  99328
#define SMEM_BYTES 164864

__device__ __forceinline__ uint32_t swz(uint32_t x) { return x ^ ((x >> 3) & 0x70); }

__device__ __forceinline__ uint32_t smem_u32(const void* p) {
    uint32_t a;
    asm("{ .reg .u64 t; cvta.to.shared.u64 t, %1; cvt.u32.u64 %0, t; }"
        : "=r"(a) : "l"(p));
    return a;
}
__device__ __forceinline__ void ldsm4(uint32_t r[4], uint32_t addr) {
    asm volatile("ldmatrix.sync.aligned.m8n8.x4.shared.b16 {%0,%1,%2,%3}, [%4];"
                 : "=r"(r[0]), "=r"(r[1]), "=r"(r[2]), "=r"(r[3]) : "r"(addr));
}
__device__ __forceinline__ void ldsm4t(uint32_t r[4], uint32_t addr) {
    asm volatile("ldmatrix.sync.aligned.m8n8.x4.trans.shared.b16 {%0,%1,%2,%3}, [%4];"
                 : "=r"(r[0]), "=r"(r[1]), "=r"(r[2]), "=r"(r[3]) : "r"(addr));
}
__device__ __forceinline__ void mma_bf16(float d[4], const uint32_t a[4],
                                         uint32_t b0, uint32_t b1) {
    asm volatile(
        "mma.sync.aligned.m16n8k16.row.col.f32.bf16.bf16.f32 "
        "{%0,%1,%2,%3}, {%4,%5,%6,%7}, {%8,%9}, {%0,%1,%2,%3};"
        : "+f"(d[0]), "+f"(d[1]), "+f"(d[2]), "+f"(d[3])
        : "r"(a[0]), "r"(a[1]), "r"(a[2]), "r"(a[3]), "r"(b0), "r"(b1));
}
__device__ __forceinline__ uint32_t packbf(float a, float b) {   // a -> low half
    __nv_bfloat162 t = __float22bfloat162_rn(make_float2(a, b));
    return *reinterpret_cast<uint32_t*>(&t);
}
__device__ __forceinline__ uint32_t packresid(float a, float b, uint32_t hi) {
    __nv_bfloat162 t = *reinterpret_cast<__nv_bfloat162*>(&hi);
    return packbf(a - __bfloat162float(t.x), b - __bfloat162float(t.y));
}
__device__ __forceinline__ void cpasync16(uint32_t dst, const void* src) {
    asm volatile("cp.async.cg.shared.global [%0], [%1], 16;"
                 :: "r"(dst), "l"(src) : "memory");
}
#define CP_COMMIT() asm volatile("cp.async.commit_group;" ::: "memory")
#define CP_WAIT0()  asm volatile("cp.async.wait_group 0;" ::: "memory")

// ---------------------------------------------------------------------------
// K0: per-row sigma transform (verified R1-R11)
// ---------------------------------------------------------------------------
__global__ void k_sig(const float* __restrict__ sigma) {
    int i = blockIdx.x * 256 + threadIdx.x;
    if (i >= NROWS) return;
    int bh = i >> 11;
    int l  = i & 2047;
    int b = bh >> 3, h = bh & 7;
    float x = sigma[((size_t)b * LL + l) * HH + h];
    float s32 = (float)(1.0 / (1.0 + exp(-5.0 * (double)x)));
    float sg  = s32 + 1e-5f;
    float p   = (float)exp((double)sg * 1.0986122886681098);
    float s   = p - 1.0f;
    g_sigv[i]   = s;
    g_coef[i]   = 1.0f / (2.5066282746310002f * s);
    g_inv2s2[i] = 1.0f / (2.0f * s * s);
}

// ---------------------------------------------------------------------------
// k_prep: one-time f32 -> bf16 hi/lo conversion of Q/K/V into swizzled
// tile scratch (byte-identical to the fused kernel's former in-smem layout).
// Grid (16, NBH), 256 threads. ~96MB read / 48MB write => ~20us.
// ---------------------------------------------------------------------------
__global__ void __launch_bounds__(256) k_prep(const float* __restrict__ Q,
                                              const float* __restrict__ K,
                                              const float* __restrict__ V) {
    int t  = blockIdx.x;              // tile index 0..15 (128 rows)
    int bh = blockIdx.y, b = bh >> 3, h = bh & 7;
    int tid = threadIdx.x;
    int e4 = tid & 15, r0 = tid >> 4;
    size_t tb = ((size_t)bh * 16 + t) * TILE_B;
    const float* Qb = Q + (size_t)b * LL * STRIDE_L + h * EE;
    const float* Kb = K + (size_t)b * LL * STRIDE_L + h * EE;
    const float* Vb = V + (size_t)b * LL * STRIDE_L + h * EE;
#pragma unroll
    for (int ps = 0; ps < 8; ps++) {
        int row = r0 + ps * 16;
        size_t gro = (size_t)(t * 128 + row) * STRIDE_L + e4 * 4;
        uint32_t sw = swz(row * 128 + e4 * 8);
        float4 q = *(const float4*)&Qb[gro];
        uint32_t qh0 = packbf(q.x, q.y), qh1 = packbf(q.z, q.w);
        *(uint2*)(g_qhi + tb + sw) = make_uint2(qh0, qh1);
        *(uint2*)(g_qlo + tb + sw) =
            make_uint2(packresid(q.x, q.y, qh0), packresid(q.z, q.w, qh1));
        float4 k = *(const float4*)&Kb[gro];
        uint32_t kh0 = packbf(k.x, k.y), kh1 = packbf(k.z, k.w);
        *(uint2*)(g_khi + tb + sw) = make_uint2(kh0, kh1);
        *(uint2*)(g_klo + tb + sw) =
            make_uint2(packresid(k.x, k.y, kh0), packresid(k.z, k.w, kh1));
        float4 v = *(const float4*)&Vb[gro];
        uint32_t vh0 = packbf(v.x, v.y), vh1 = packbf(v.z, v.w);
        *(uint2*)(g_vhi + tb + sw) = make_uint2(vh0, vh1);
        *(uint2*)(g_vlo + tb + sw) =
            make_uint2(packresid(v.x, v.y, vh0), packresid(v.z, v.w, vh1));
    }
}

// ---------------------------------------------------------------------------
// Fused flash kernel: no conversion phase; double-buffered cp.async of
// pre-swizzled bf16 tiles; one barrier per tile; diagonal-tile jp/kk skip.
// 256 threads, 8 warps; warp w owns output rows [w*16, w*16+16).
// ---------------------------------------------------------------------------
__global__ void __launch_bounds__(256, 1)
k_fused(float* __restrict__ series, float* __restrict__ out) {
    extern __shared__ __align__(1024) char smem[];
    float* smf = (float*)smem;
    uint32_t sb = smem_u32(smem);
    int tid = threadIdx.x, wid = tid >> 5, lane = tid & 31;
    int bh = blockIdx.y, b = bh >> 3, h = bh & 7;
    int ti = 15 - blockIdx.x, l0 = ti * 128;
    int R0 = wid * 16;
    int g = lane >> 2, tig = lane & 3;
    int L8 = lane & 7, m = lane >> 3;

    float* Srow = series + ((size_t)bh * LL + l0) * LL;
    size_t tbase = (size_t)bh * 16 * TILE_B;

    // ---- cp.async: Q tiles (hi+lo) + tile-0 K/V group into BUF0 ----
    {
        size_t tq = tbase + (size_t)ti * TILE_B;
        uint32_t o = tid * 64;
#pragma unroll
        for (int i = 0; i < 4; i++) {
            cpasync16(sb + OFF_QHI + o + i * 16, g_qhi + tq + o + i * 16);
            cpasync16(sb + OFF_QLO + o + i * 16, g_qlo + tq + o + i * 16);
        }
        size_t t0 = tbase;   // tile tj=0
#pragma unroll
        for (int i = 0; i < 4; i++) {
            cpasync16(sb + OFF_BUF0 +         o + i * 16, g_khi + t0 + o + i * 16);
            cpasync16(sb + OFF_BUF0 + 16384 + o + i * 16, g_klo + t0 + o + i * 16);
            cpasync16(sb + OFF_BUF0 + 32768 + o + i * 16, g_vhi + t0 + o + i * 16);
            cpasync16(sb + OFF_BUF0 + 49152 + o + i * 16, g_vlo + t0 + o + i * 16);
        }
        CP_COMMIT();
    }
    CP_WAIT0();
    __syncthreads();

    // ---- Preload Q fragments (4 k-steps, hi+lo) ----
    uint32_t qh[4][4], ql[4][4];
    {
        uint32_t ro = (uint32_t)(R0 + (m & 1) * 8 + L8) * 128 + (m >> 1) * 16;
#pragma unroll
        for (int ks = 0; ks < 4; ks++) {
            uint32_t sw = swz(ro + ks * 32);
            ldsm4(qh[ks], sb + OFF_QHI + sw);
            ldsm4(ql[ks], sb + OFF_QLO + sw);
        }
    }

    float oacc[8][4];
#pragma unroll
    for (int t = 0; t < 8; t++)
#pragma unroll
        for (int c = 0; c < 4; c++) oacc[t][c] = 0.f;
    float rs0 = 0.f, rs1 = 0.f;
    int gl0 = l0 + R0 + g, gl1 = gl0 + 8;

    uint32_t k_ro = (uint32_t)((m >> 1) * 8 + L8) * 128 + (m & 1) * 16;   // K (no trans)
    uint32_t v_ro = (uint32_t)((m & 1) * 8 + L8) * 128 + (m >> 1) * 16;   // V (trans)

    for (int tj = 0; tj <= ti; tj++) {
        int j0 = tj * 128;
        uint32_t kb = sb + (((tj & 1) ? OFF_BUF1 : OFF_BUF0));
        CP_WAIT0();        // tile tj's group (issued last iter / preloop) done
        __syncthreads();   // all warps done with the buffer we're about to refill

        // ---- prefetch tile tj+1 into the other buffer ----
        if (tj < ti) {
            uint32_t nb = sb + (((tj & 1) ? OFF_BUF0 : OFF_BUF1));
            size_t tn = tbase + (size_t)(tj + 1) * TILE_B;
            uint32_t o = tid * 64;
#pragma unroll
            for (int i = 0; i < 4; i++) {
                cpasync16(nb +         o + i * 16, g_khi + tn + o + i * 16);
                cpasync16(nb + 16384 + o + i * 16, g_klo + tn + o + i * 16);
                cpasync16(nb + 32768 + o + i * 16, g_vhi + tn + o + i * 16);
                cpasync16(nb + 49152 + o + i * 16, g_vlo + tn + o + i * 16);
            }
            CP_COMMIT();
        }

        // Diagonal tile: warp w only needs jp,kk <= w; rest is fully masked.
        int wlim = (tj == ti) ? wid : 7;

        // ---- GEMM1: S = Q.K^T via 3-term bf16 split ----
        float sacc[16][4];
#pragma unroll
        for (int t = 0; t < 16; t++)
#pragma unroll
            for (int c = 0; c < 4; c++) sacc[t][c] = 0.f;

#pragma unroll
        for (int jp = 0; jp < 8; jp++) {
            if (jp > wlim) break;
#pragma unroll
            for (int ks = 0; ks < 4; ks++) {
                uint32_t sw = swz(k_ro + (uint32_t)jp * 16 * 128 + ks * 32);
                uint32_t bh_[4], bl_[4];
                ldsm4(bh_, kb + sw);
                ldsm4(bl_, kb + 16384 + sw);
                mma_bf16(sacc[2 * jp],     qh[ks], bh_[0], bh_[1]);
                mma_bf16(sacc[2 * jp],     qh[ks], bl_[0], bl_[1]);
                mma_bf16(sacc[2 * jp],     ql[ks], bh_[0], bh_[1]);
                mma_bf16(sacc[2 * jp + 1], qh[ks], bh_[2], bh_[3]);
                mma_bf16(sacc[2 * jp + 1], qh[ks], bl_[2], bl_[3]);
                mma_bf16(sacc[2 * jp + 1], ql[ks], bh_[2], bh_[3]);
            }
        }

        // ---- softmax numerator + series store (unnormalized) ----
#pragma unroll
        for (int t = 0; t < 16; t++) {
            int gj = j0 + t * 8 + tig * 2;
            if ((t >> 1) > wlim) {     // fully-masked diag chunk: plain zeros
                float2 z = make_float2(0.f, 0.f);
                *(float2*)&Srow[(size_t)(R0 + g) * LL + gj]     = z;
                *(float2*)&Srow[(size_t)(R0 + 8 + g) * LL + gj] = z;
                continue;
            }
            float e0 = __expf(SCALEF * sacc[t][0]);
            float e1 = __expf(SCALEF * sacc[t][1]);
            float e2 = __expf(SCALEF * sacc[t][2]);
            float e3 = __expf(SCALEF * sacc[t][3]);
            e0 = (gj     <= gl0) ? e0 : 0.f;
            e1 = (gj + 1 <= gl0) ? e1 : 0.f;
            e2 = (gj     <= gl1) ? e2 : 0.f;
            e3 = (gj + 1 <= gl1) ? e3 : 0.f;
            rs0 += e0 + e1;
            rs1 += e2 + e3;
            sacc[t][0] = e0; sacc[t][1] = e1; sacc[t][2] = e2; sacc[t][3] = e3;
            *(float2*)&Srow[(size_t)(R0 + g) * LL + gj]     = make_float2(e0, e1);
            *(float2*)&Srow[(size_t)(R0 + 8 + g) * LL + gj] = make_float2(e2, e3);
        }

        // ---- GEMM2: O += P.V, P fragments straight from registers ----
#pragma unroll
        for (int kk = 0; kk < 8; kk++) {
            if (kk > wlim) break;      // P == 0 beyond the diagonal
            const float* x = sacc[2 * kk];
            const float* y = sacc[2 * kk + 1];
            uint32_t ah[4], al[4];
            ah[0] = packbf(x[0], x[1]); ah[1] = packbf(x[2], x[3]);
            ah[2] = packbf(y[0], y[1]); ah[3] = packbf(y[2], y[3]);
            al[0] = packresid(x[0], x[1], ah[0]);
            al[1] = packresid(x[2], x[3], ah[1]);
            al[2] = packresid(y[0], y[1], ah[2]);
            al[3] = packresid(y[2], y[3], ah[3]);
#pragma unroll
            for (int ep = 0; ep < 4; ep++) {
                uint32_t sw = swz(v_ro + (uint32_t)kk * 16 * 128 + ep * 32);
                uint32_t vh_[4], vl_[4];
                ldsm4t(vh_, kb + 32768 + sw);
                ldsm4t(vl_, kb + 49152 + sw);
                mma_bf16(oacc[2 * ep],     ah, vh_[0], vh_[1]);
                mma_bf16(oacc[2 * ep],     ah, vl_[0], vl_[1]);
                mma_bf16(oacc[2 * ep],     al, vh_[0], vh_[1]);
                mma_bf16(oacc[2 * ep + 1], ah, vh_[2], vh_[3]);
                mma_bf16(oacc[2 * ep + 1], ah, vl_[2], vl_[3]);
                mma_bf16(oacc[2 * ep + 1], al, vh_[2], vh_[3]);
            }
        }
    }

    // ---- row sums: reduce over the 4 tig lanes ----
    rs0 += __shfl_xor_sync(0xFFFFFFFF, rs0, 1);
    rs0 += __shfl_xor_sync(0xFFFFFFFF, rs0, 2);
    rs1 += __shfl_xor_sync(0xFFFFFFFF, rs1, 1);
    rs1 += __shfl_xor_sync(0xFFFFFFFF, rs1, 2);
    float inv0 = 1.0f / rs0, inv1 = 1.0f / rs1;
    if (tig == 0) {
        smf[OFF_INV / 4 + R0 + g]     = inv0;
        smf[OFF_INV / 4 + R0 + 8 + g] = inv1;
    }

    // ---- O epilogue (own rows) ----
#pragma unroll
    for (int t = 0; t < 8; t++) {
        int col = t * 8 + tig * 2;
        float* d0 = out + (((size_t)b * LL + gl0) * HH + h) * EE + col;
        float* d1 = out + (((size_t)b * LL + gl1) * HH + h) * EE + col;
        *(float2*)d0 = make_float2(oacc[t][0] * inv0, oacc[t][1] * inv0);
        *(float2*)d1 = make_float2(oacc[t][2] * inv1, oacc[t][3] * inv1);
    }
    __syncthreads();

    // ---- in-place series renormalization (rows of this CTA's block) ----
    {
        int ncols4 = (l0 + 128) >> 2;
        for (int rr = wid; rr < 128; rr += 8) {
            float inv = smf[OFF_INV / 4 + rr];
            float* rowp = series + ((size_t)bh * LL + l0 + rr) * LL;
            for (int c4 = lane; c4 < ncols4; c4 += 32) {
                float4 s = *(float4*)&rowp[c4 * 4];
                s.x *= inv; s.y *= inv; s.z *= inv; s.w *= inv;
                *(float4*)&rowp[c4 * 4] = s;
            }
        }
    }
}

// ---------------------------------------------------------------------------
// k_prior: prior + sig everywhere; zero series in strictly-upper tiles.
// Writes disjoint from k_fused's -> safe to run concurrently.
// ---------------------------------------------------------------------------
__global__ void __launch_bounds__(256) k_prior(float* __restrict__ prior,
                                               float* __restrict__ sig,
                                               float* __restrict__ series) {
    int bh = blockIdx.z;
    int ti = blockIdx.y, tj = blockIdx.x;
    int l0 = ti * 128, j0 = tj * 128;
    bool upper = (tj > ti);
    int tid = threadIdx.x;
    int c4 = (tid & 31) * 4;
    int r0 = tid >> 5;
#pragma unroll 4
    for (int it = 0; it < 16; it++) {
        int lr = r0 + it * 8;
        int gl = l0 + lr;
        size_t rowi = (size_t)bh * LL + gl;
        float coef = g_coef[rowi];
        float i2s  = g_inv2s2[rowi];
        float sv   = g_sigv[rowi];
        float p[4];
#pragma unroll
        for (int c = 0; c < 4; c++) {
            int gj = j0 + c4 + c;
            int d  = gl - gj;
            float d2 = (float)(d * d);
            p[c] = coef * __expf(-d2 * i2s);
        }
        size_t idx = rowi * LL + j0 + c4;
        *(float4*)&prior[idx] = make_float4(p[0], p[1], p[2], p[3]);
        *(float4*)&sig[idx]   = make_float4(sv, sv, sv, sv);
        if (upper)
            *(float4*)&series[idx] = make_float4(0.f, 0.f, 0.f, 0.f);
    }
}

// ---------------------------------------------------------------------------
// Launcher: k_sig + k_prep, then FORK -> {k_fused main, k_prior side} -> JOIN.
// ---------------------------------------------------------------------------
extern "C" void kernel_launch(void* const* d_in, const int* in_sizes, int n_in,
                              void* d_out, int out_size) {
    const float* Q = (const float*)d_in[0];
    const float* K = (const float*)d_in[1];
    const float* V = (const float*)d_in[2];
    const float* S = (const float*)d_in[3];
    float* out = (float*)d_out;

    float* outV      = out;
    float* outSeries = outV + (size_t)BB * LL * HH * EE;
    float* outPrior  = outSeries + (size_t)NBH * LL * LL;
    float* outSig    = outPrior + (size_t)NBH * LL * LL;

    cudaFuncSetAttribute(k_fused, cudaFuncAttributeMaxDynamicSharedMemorySize,
                         SMEM_BYTES);

    cudaStream_t side;
    cudaStreamCreateWithFlags(&side, cudaStreamNonBlocking);
    cudaEvent_t eFork, eJoin;
    cudaEventCreateWithFlags(&eFork, cudaEventDisableTiming);
    cudaEventCreateWithFlags(&eJoin, cudaEventDisableTiming);

    k_sig<<<NROWS / 256, 256>>>(S);
    k_prep<<<dim3(16, NBH), 256>>>(Q, K, V);

    // fork: side stream depends on k_sig/k_prep
    cudaEventRecord(eFork, 0);
    cudaStreamWaitEvent(side, eFork, 0);

    // concurrent pair
    k_prior<<<dim3(16, 16, NBH), 256, 0, side>>>(outPrior, outSig, outSeries);
    cudaEventRecord(eJoin, side);
    k_fused<<<dim3(16, NBH), 256, SMEM_BYTES>>>(outSeries, outV);

    // join: main stream waits for k_prior before harness reads d_out
    cudaStreamWaitEvent(0, eJoin, 0);
}

// round 14
// speedup vs baseline: 1.0457x; 1.0457x over previous
#include <cuda_runtime.h>
#include <cuda_bf16.h>
#include <cstdint>
#include <math.h>

// Problem constants (B=4, L=2048, H=8, E=64)
#define BB 4
#define LL 2048
#define HH 8
#define EE 64
#define NBH (BB*HH)           // 32
#define NROWS (NBH*LL)        // 65536
#define SCALEF 0.125f
#define STRIDE_L (HH*EE)      // 512

// Scratch (device globals)
__device__ float g_sigv[NROWS];
__device__ float g_coef[NROWS];
__device__ float g_inv2s2[NROWS];

// ---- smem layout (bytes). bf16 tiles: 128x64 = 16384 B each, SW128 ----
#define OFF_INV   0            // 128 f32 rowsum reciprocals
#define OFF_QHI   1024
#define OFF_QLO   17408
#define OFF_KHI   33792
#define OFF_KLO   50176
#define OFF_VHI   66560
#define OFF_VLO   82944
#define OFF_SK    99328        // f32 staging K: 128 rows x 256 B
#define OFF_SV    132096       // f32 staging V: 128 rows x 256 B
#define SMEM_BYTES 164864

__device__ __forceinline__ uint32_t swz(uint32_t x) { return x ^ ((x >> 3) & 0x70); }

__device__ __forceinline__ uint32_t smem_u32(const void* p) {
    uint32_t a;
    asm("{ .reg .u64 t; cvta.to.shared.u64 t, %1; cvt.u32.u64 %0, t; }"
        : "=r"(a) : "l"(p));
    return a;
}
__device__ __forceinline__ void ldsm4(uint32_t r[4], uint32_t addr) {
    asm volatile("ldmatrix.sync.aligned.m8n8.x4.shared.b16 {%0,%1,%2,%3}, [%4];"
                 : "=r"(r[0]), "=r"(r[1]), "=r"(r[2]), "=r"(r[3]) : "r"(addr));
}
__device__ __forceinline__ void ldsm4t(uint32_t r[4], uint32_t addr) {
    asm volatile("ldmatrix.sync.aligned.m8n8.x4.trans.shared.b16 {%0,%1,%2,%3}, [%4];"
                 : "=r"(r[0]), "=r"(r[1]), "=r"(r[2]), "=r"(r[3]) : "r"(addr));
}
__device__ __forceinline__ void mma_bf16(float d[4], const uint32_t a[4],
                                         uint32_t b0, uint32_t b1) {
    asm volatile(
        "mma.sync.aligned.m16n8k16.row.col.f32.bf16.bf16.f32 "
        "{%0,%1,%2,%3}, {%4,%5,%6,%7}, {%8,%9}, {%0,%1,%2,%3};"
        : "+f"(d[0]), "+f"(d[1]), "+f"(d[2]), "+f"(d[3])
        : "r"(a[0]), "r"(a[1]), "r"(a[2]), "r"(a[3]), "r"(b0), "r"(b1));
}
__device__ __forceinline__ uint32_t packbf(float a, float b) {   // a -> low half
    __nv_bfloat162 t = __float22bfloat162_rn(make_float2(a, b));
    return *reinterpret_cast<uint32_t*>(&t);
}
__device__ __forceinline__ uint32_t packresid(float a, float b, uint32_t hi) {
    __nv_bfloat162 t = *reinterpret_cast<__nv_bfloat162*>(&hi);
    return packbf(a - __bfloat162float(t.x), b - __bfloat162float(t.y));
}
__device__ __forceinline__ void cpasync16(uint32_t dst, const void* src) {
    asm volatile("cp.async.cg.shared.global [%0], [%1], 16;"
                 :: "r"(dst), "l"(src) : "memory");
}
#define CP_COMMIT() asm volatile("cp.async.commit_group;" ::: "memory")
#define CP_WAIT0()  asm volatile("cp.async.wait_group 0;" ::: "memory")

// ---------------------------------------------------------------------------
// K0: per-row sigma transform (verified R1-R11)
// ---------------------------------------------------------------------------
__global__ void k_sig(const float* __restrict__ sigma) {
    int i = blockIdx.x * 256 + threadIdx.x;
    if (i >= NROWS) return;
    int bh = i >> 11;
    int l  = i & 2047;
    int b = bh >> 3, h = bh & 7;
    float x = sigma[((size_t)b * LL + l) * HH + h];
    float s32 = (float)(1.0 / (1.0 + exp(-5.0 * (double)x)));
    float sg  = s32 + 1e-5f;
    float p   = (float)exp((double)sg * 1.0986122886681098);
    float s   = p - 1.0f;
    g_sigv[i]   = s;
    g_coef[i]   = 1.0f / (2.5066282746310002f * s);
    g_inv2s2[i] = 1.0f / (2.0f * s * s);
}

// ---------------------------------------------------------------------------
// Fused flash kernel — R8/R11 structure with ONE change: GEMM1 loop nest is
// ks-outer / jp-inner so consecutive MMAs rotate over all 16 accumulators
// (same-accumulator issue distance 1 -> ~48; RAW chains hidden at 2 w/SMSP).
// ---------------------------------------------------------------------------
__global__ void __launch_bounds__(256, 1)
k_fused(const float* __restrict__ Q, const float* __restrict__ K,
        const float* __restrict__ V, float* __restrict__ series,
        float* __restrict__ out) {
    extern __shared__ __align__(1024) char smem[];
    float* smf = (float*)smem;
    uint32_t sb = smem_u32(smem);
    int tid = threadIdx.x, wid = tid >> 5, lane = tid & 31;
    int bh = blockIdx.y, b = bh >> 3, h = bh & 7;
    int ti = 15 - blockIdx.x, l0 = ti * 128;
    int R0 = wid * 16;
    int g = lane >> 2, tig = lane & 3;
    int L8 = lane & 7, m = lane >> 3;

    const float* Qb = Q + (size_t)b * LL * STRIDE_L + h * EE;
    const float* Kb = K + (size_t)b * LL * STRIDE_L + h * EE;
    const float* Vb = V + (size_t)b * LL * STRIDE_L + h * EE;
    float* Srow = series + ((size_t)bh * LL + l0) * LL;

    int e4 = tid & 15, r0 = tid >> 4;   // shared thread mapping for loads

    // ---- prefetch tile 0 K/V into f32 staging ----
    {
#pragma unroll
        for (int ps = 0; ps < 8; ps++) {
            int row = r0 + ps * 16;
            cpasync16(sb + OFF_SK + row * 256 + e4 * 16,
                      Kb + (size_t)row * STRIDE_L + e4 * 4);
            cpasync16(sb + OFF_SV + row * 256 + e4 * 16,
                      Vb + (size_t)row * STRIDE_L + e4 * 4);
        }
        CP_COMMIT();
    }

    // ---- Q tile -> smem bf16 hi/lo, [l][e], SW128 rows of 128B ----
    {
#pragma unroll
        for (int ps = 0; ps < 8; ps++) {
            int row = r0 + ps * 16;
            float4 v = *(const float4*)&Qb[(size_t)(l0 + row) * STRIDE_L + e4 * 4];
            uint32_t h0 = packbf(v.x, v.y), h1 = packbf(v.z, v.w);
            uint32_t sw = swz(row * 128 + e4 * 8);
            *(uint2*)(smem + OFF_QHI + sw) = make_uint2(h0, h1);
            *(uint2*)(smem + OFF_QLO + sw) =
                make_uint2(packresid(v.x, v.y, h0), packresid(v.z, v.w, h1));
        }
    }
    __syncthreads();

    // ---- Preload Q fragments (4 k-steps, hi+lo) ----
    uint32_t qh[4][4], ql[4][4];
    {
        uint32_t ro = (uint32_t)(R0 + (m & 1) * 8 + L8) * 128 + (m >> 1) * 16;
#pragma unroll
        for (int ks = 0; ks < 4; ks++) {
            uint32_t sw = swz(ro + ks * 32);
            ldsm4(qh[ks], sb + OFF_QHI + sw);
            ldsm4(ql[ks], sb + OFF_QLO + sw);
        }
    }

    float oacc[8][4];
#pragma unroll
    for (int t = 0; t < 8; t++)
#pragma unroll
        for (int c = 0; c < 4; c++) oacc[t][c] = 0.f;
    float rs0 = 0.f, rs1 = 0.f;
    int gl0 = l0 + R0 + g, gl1 = gl0 + 8;

    // lane-offsets for B-fragment ldmatrix addresses
    uint32_t k_ro = (uint32_t)((m >> 1) * 8 + L8) * 128 + (m & 1) * 16;   // K (no trans)
    uint32_t v_ro = (uint32_t)((m & 1) * 8 + L8) * 128 + (m >> 1) * 16;   // V (trans)

    for (int tj = 0; tj <= ti; tj++) {
        int j0 = tj * 128;
        CP_WAIT0();
        __syncthreads();   // staging visible to all; previous tile's smem reads done

        // ---- convert staged f32 -> bf16 hi/lo smem tiles (K and V) ----
        {
#pragma unroll
            for (int ps = 0; ps < 8; ps++) {
                int row = r0 + ps * 16;
                float4 v = *(const float4*)(smem + OFF_SK + row * 256 + e4 * 16);
                uint32_t h0 = packbf(v.x, v.y), h1 = packbf(v.z, v.w);
                uint32_t sw = swz(row * 128 + e4 * 8);
                *(uint2*)(smem + OFF_KHI + sw) = make_uint2(h0, h1);
                *(uint2*)(smem + OFF_KLO + sw) =
                    make_uint2(packresid(v.x, v.y, h0), packresid(v.z, v.w, h1));
                float4 w = *(const float4*)(smem + OFF_SV + row * 256 + e4 * 16);
                uint32_t g0 = packbf(w.x, w.y), g1 = packbf(w.z, w.w);
                *(uint2*)(smem + OFF_VHI + sw) = make_uint2(g0, g1);
                *(uint2*)(smem + OFF_VLO + sw) =
                    make_uint2(packresid(w.x, w.y, g0), packresid(w.z, w.w, g1));
            }
        }
        __syncthreads();   // converts visible; staging free for reuse

        // ---- prefetch tile tj+1 (overlaps entire MMA phase below) ----
        if (tj < ti) {
            int jn = j0 + 128;
#pragma unroll
            for (int ps = 0; ps < 8; ps++) {
                int row = r0 + ps * 16;
                cpasync16(sb + OFF_SK + row * 256 + e4 * 16,
                          Kb + (size_t)(jn + row) * STRIDE_L + e4 * 4);
                cpasync16(sb + OFF_SV + row * 256 + e4 * 16,
                          Vb + (size_t)(jn + row) * STRIDE_L + e4 * 4);
            }
            CP_COMMIT();
        }

        // ---- GEMM1: S = Q.K^T via 3-term bf16 split.
        //      ks OUTER / jp INNER: accumulators rotate -> MMA ILP ~16. ----
        float sacc[16][4];
#pragma unroll
        for (int t = 0; t < 16; t++)
#pragma unroll
            for (int c = 0; c < 4; c++) sacc[t][c] = 0.f;

#pragma unroll
        for (int ks = 0; ks < 4; ks++) {
#pragma unroll
            for (int jp = 0; jp < 8; jp++) {
                uint32_t sw = swz(k_ro + (uint32_t)jp * 16 * 128 + ks * 32);
                uint32_t bh_[4], bl_[4];
                ldsm4(bh_, sb + OFF_KHI + sw);
                ldsm4(bl_, sb + OFF_KLO + sw);
                mma_bf16(sacc[2 * jp],     qh[ks], bh_[0], bh_[1]);
                mma_bf16(sacc[2 * jp],     qh[ks], bl_[0], bl_[1]);
                mma_bf16(sacc[2 * jp],     ql[ks], bh_[0], bh_[1]);
                mma_bf16(sacc[2 * jp + 1], qh[ks], bh_[2], bh_[3]);
                mma_bf16(sacc[2 * jp + 1], qh[ks], bl_[2], bl_[3]);
                mma_bf16(sacc[2 * jp + 1], ql[ks], bh_[2], bh_[3]);
            }
        }

        // ---- softmax numerator + series store (unnormalized) ----
#pragma unroll
        for (int t = 0; t < 16; t++) {
            int gj = j0 + t * 8 + tig * 2;
            float e0 = __expf(SCALEF * sacc[t][0]);
            float e1 = __expf(SCALEF * sacc[t][1]);
            float e2 = __expf(SCALEF * sacc[t][2]);
            float e3 = __expf(SCALEF * sacc[t][3]);
            e0 = (gj     <= gl0) ? e0 : 0.f;
            e1 = (gj + 1 <= gl0) ? e1 : 0.f;
            e2 = (gj     <= gl1) ? e2 : 0.f;
            e3 = (gj + 1 <= gl1) ? e3 : 0.f;
            rs0 += e0 + e1;
            rs1 += e2 + e3;
            sacc[t][0] = e0; sacc[t][1] = e1; sacc[t][2] = e2; sacc[t][3] = e3;
            *(float2*)&Srow[(size_t)(R0 + g) * LL + gj]     = make_float2(e0, e1);
            *(float2*)&Srow[(size_t)(R0 + 8 + g) * LL + gj] = make_float2(e2, e3);
        }

        // ---- GEMM2: O += P.V, P fragments straight from registers ----
#pragma unroll
        for (int kk = 0; kk < 8; kk++) {
            const float* x = sacc[2 * kk];
            const float* y = sacc[2 * kk + 1];
            uint32_t ah[4], al[4];
            ah[0] = packbf(x[0], x[1]); ah[1] = packbf(x[2], x[3]);
            ah[2] = packbf(y[0], y[1]); ah[3] = packbf(y[2], y[3]);
            al[0] = packresid(x[0], x[1], ah[0]);
            al[1] = packresid(x[2], x[3], ah[1]);
            al[2] = packresid(y[0], y[1], ah[2]);
            al[3] = packresid(y[2], y[3], ah[3]);
#pragma unroll
            for (int ep = 0; ep < 4; ep++) {
                uint32_t sw = swz(v_ro + (uint32_t)kk * 16 * 128 + ep * 32);
                uint32_t vh_[4], vl_[4];
                ldsm4t(vh_, sb + OFF_VHI + sw);
                ldsm4t(vl_, sb + OFF_VLO + sw);
                mma_bf16(oacc[2 * ep],     ah, vh_[0], vh_[1]);
                mma_bf16(oacc[2 * ep],     ah, vl_[0], vl_[1]);
                mma_bf16(oacc[2 * ep],     al, vh_[0], vh_[1]);
                mma_bf16(oacc[2 * ep + 1], ah, vh_[2], vh_[3]);
                mma_bf16(oacc[2 * ep + 1], ah, vl_[2], vl_[3]);
                mma_bf16(oacc[2 * ep + 1], al, vh_[2], vh_[3]);
            }
        }
    }

    // ---- row sums: reduce over the 4 tig lanes ----
    rs0 += __shfl_xor_sync(0xFFFFFFFF, rs0, 1);
    rs0 += __shfl_xor_sync(0xFFFFFFFF, rs0, 2);
    rs1 += __shfl_xor_sync(0xFFFFFFFF, rs1, 1);
    rs1 += __shfl_xor_sync(0xFFFFFFFF, rs1, 2);
    float inv0 = 1.0f / rs0, inv1 = 1.0f / rs1;
    if (tig == 0) {
        smf[OFF_INV / 4 + R0 + g]     = inv0;
        smf[OFF_INV / 4 + R0 + 8 + g] = inv1;
    }

    // ---- O epilogue (own rows; no cross-warp data needed) ----
#pragma unroll
    for (int t = 0; t < 8; t++) {
        int col = t * 8 + tig * 2;
        float* d0 = out + (((size_t)b * LL + gl0) * HH + h) * EE + col;
        float* d1 = out + (((size_t)b * LL + gl1) * HH + h) * EE + col;
        *(float2*)d0 = make_float2(oacc[t][0] * inv0, oacc[t][1] * inv0);
        *(float2*)d1 = make_float2(oacc[t][2] * inv1, oacc[t][3] * inv1);
    }
    __syncthreads();

    // ---- in-place series renormalization (rows of this CTA's block) ----
    {
        int ncols4 = (l0 + 128) >> 2;
        for (int rr = wid; rr < 128; rr += 8) {
            float inv = smf[OFF_INV / 4 + rr];
            float* rowp = series + ((size_t)bh * LL + l0 + rr) * LL;
            for (int c4 = lane; c4 < ncols4; c4 += 32) {
                float4 s = *(float4*)&rowp[c4 * 4];
                s.x *= inv; s.y *= inv; s.z *= inv; s.w *= inv;
                *(float4*)&rowp[c4 * 4] = s;
            }
        }
    }
}

// ---------------------------------------------------------------------------
// k_prior: prior + sig everywhere; zero series in strictly-upper tiles.
// Writes disjoint from k_fused's -> safe to run concurrently with it.
// ---------------------------------------------------------------------------
__global__ void __launch_bounds__(256) k_prior(float* __restrict__ prior,
                                               float* __restrict__ sig,
                                               float* __restrict__ series) {
    int bh = blockIdx.z;
    int ti = blockIdx.y, tj = blockIdx.x;
    int l0 = ti * 128, j0 = tj * 128;
    bool upper = (tj > ti);
    int tid = threadIdx.x;
    int c4 = (tid & 31) * 4;
    int r0 = tid >> 5;
#pragma unroll 4
    for (int it = 0; it < 16; it++) {
        int lr = r0 + it * 8;
        int gl = l0 + lr;
        size_t rowi = (size_t)bh * LL + gl;
        float coef = g_coef[rowi];
        float i2s  = g_inv2s2[rowi];
        float sv   = g_sigv[rowi];
        float p[4];
#pragma unroll
        for (int c = 0; c < 4; c++) {
            int gj = j0 + c4 + c;
            int d  = gl - gj;
            float d2 = (float)(d * d);
            p[c] = coef * __expf(-d2 * i2s);
        }
        size_t idx = rowi * LL + j0 + c4;
        *(float4*)&prior[idx] = make_float4(p[0], p[1], p[2], p[3]);
        *(float4*)&sig[idx]   = make_float4(sv, sv, sv, sv);
        if (upper)
            *(float4*)&series[idx] = make_float4(0.f, 0.f, 0.f, 0.f);
    }
}

// ---------------------------------------------------------------------------
// Launcher: k_sig, then FORK -> {k_fused main, k_prior side} -> JOIN.
// Streams/events created per call, intentionally not destroyed (host-side
// objects only; destroying a forked stream during capture invalidates it).
// ---------------------------------------------------------------------------
extern "C" void kernel_launch(void* const* d_in, const int* in_sizes, int n_in,
                              void* d_out, int out_size) {
    const float* Q = (const float*)d_in[0];
    const float* K = (const float*)d_in[1];
    const float* V = (const float*)d_in[2];
    const float* S = (const float*)d_in[3];
    float* out = (float*)d_out;

    float* outV      = out;
    float* outSeries = outV + (size_t)BB * LL * HH * EE;
    float* outPrior  = outSeries + (size_t)NBH * LL * LL;
    float* outSig    = outPrior + (size_t)NBH * LL * LL;

    cudaFuncSetAttribute(k_fused, cudaFuncAttributeMaxDynamicSharedMemorySize,
                         SMEM_BYTES);

    cudaStream_t side;
    cudaStreamCreateWithFlags(&side, cudaStreamNonBlocking);
    cudaEvent_t eFork, eJoin;
    cudaEventCreateWithFlags(&eFork, cudaEventDisableTiming);
    cudaEventCreateWithFlags(&eJoin, cudaEventDisableTiming);

    k_sig<<<NROWS / 256, 256>>>(S);

    // fork: side stream depends on k_sig
    cudaEventRecord(eFork, 0);
    cudaStreamWaitEvent(side, eFork, 0);

    // concurrent pair
    k_prior<<<dim3(16, 16, NBH), 256, 0, side>>>(outPrior, outSig, outSeries);
    cudaEventRecord(eJoin, side);
    k_fused<<<dim3(16, NBH), 256, SMEM_BYTES>>>(Q, K, V, outSeries, outV);

    // join: main stream waits for k_prior before harness reads d_out
    cudaStreamWaitEvent(0, eJoin, 0);
}